// round 13
// baseline (speedup 1.0000x reference)
#include <cuda_runtime.h>

// Problem constants
#define Bb   2
#define Ss   2048
#define Dd   1024
#define Hh   16
#define HD   64
#define Mm   (Bb*Ss)          // 4096
#define EPS  1e-8f

// Scratch (allocation-free rule: __device__ globals)
__device__ float g_q[Bb*Hh*Ss*HD];
__device__ float g_k[Bb*Hh*Ss*HD];
__device__ float g_v[Bb*Hh*Ss*HD];
__device__ float g_o[Mm*Dd];

// ---------------------------------------------------------------------------
// SGEMM core: C[128x128] tile of A[M,K] * W[N,K]^T  (both K-contiguous, "NT")
// 256 threads, 8x8 micro-tile per thread, BK=8, double-buffered smem:
// one barrier per k-step, next-tile LDG issued before the FFMA block.
// ---------------------------------------------------------------------------
__device__ __forceinline__ void gemm_tile(
    const float* __restrict__ A, const float* __restrict__ W,
    int m0, int n0, float acc[8][8])
{
    __shared__ float As[2][8][128];
    __shared__ float Bs[2][8][128];
    const int tid = threadIdx.x;
    const int tx  = tid & 15, ty = tid >> 4;
    const int lrow = tid >> 1;            // 0..127
    const int lc4  = (tid & 1) * 4;       // 0 or 4
    const float* aptr = A + (size_t)(m0 + lrow) * Dd + lc4;
    const float* bptr = W + (size_t)(n0 + lrow) * Dd + lc4;

    // prologue: fill buffer 0
    float4 av = *(const float4*)(aptr);
    float4 bv = *(const float4*)(bptr);
    As[0][lc4+0][lrow] = av.x; As[0][lc4+1][lrow] = av.y;
    As[0][lc4+2][lrow] = av.z; As[0][lc4+3][lrow] = av.w;
    Bs[0][lc4+0][lrow] = bv.x; Bs[0][lc4+1][lrow] = bv.y;
    Bs[0][lc4+2][lrow] = bv.z; Bs[0][lc4+3][lrow] = bv.w;
    __syncthreads();

    int buf = 0;
    for (int k0 = 0; k0 < Dd; k0 += 8) {
        const bool has_next = (k0 + 8) < Dd;
        if (has_next) {
            // issue next tile's loads; latency hides under the FFMA block
            av = *(const float4*)(aptr + k0 + 8);
            bv = *(const float4*)(bptr + k0 + 8);
        }
        #pragma unroll
        for (int k = 0; k < 8; k++) {
            float a[8], b[8];
            *(float4*)&a[0] = *(const float4*)&As[buf][k][ty*8];
            *(float4*)&a[4] = *(const float4*)&As[buf][k][ty*8+4];
            *(float4*)&b[0] = *(const float4*)&Bs[buf][k][tx*8];
            *(float4*)&b[4] = *(const float4*)&Bs[buf][k][tx*8+4];
            #pragma unroll
            for (int i = 0; i < 8; i++)
                #pragma unroll
                for (int j = 0; j < 8; j++)
                    acc[i][j] += a[i] * b[j];
        }
        if (has_next) {
            const int nb = buf ^ 1;
            As[nb][lc4+0][lrow] = av.x; As[nb][lc4+1][lrow] = av.y;
            As[nb][lc4+2][lrow] = av.z; As[nb][lc4+3][lrow] = av.w;
            Bs[nb][lc4+0][lrow] = bv.x; Bs[nb][lc4+1][lrow] = bv.y;
            Bs[nb][lc4+2][lrow] = bv.z; Bs[nb][lc4+3][lrow] = bv.w;
            __syncthreads();
            buf = nb;
        }
    }
}

// ---------------------------------------------------------------------------
// Fused QKV projection. gridDim.z = 3 selects (W, bias, dst).
// Stores into [b, h, s, hd] layout for the attention kernel.
// ---------------------------------------------------------------------------
__global__ __launch_bounds__(256) void qkv_kernel(
    const float* __restrict__ x,
    const float* __restrict__ wq, const float* __restrict__ bq,
    const float* __restrict__ wk, const float* __restrict__ bk,
    const float* __restrict__ wv, const float* __restrict__ bv)
{
    const float* W; const float* bias; float* dst;
    if (blockIdx.z == 0)      { W = wq; bias = bq; dst = g_q; }
    else if (blockIdx.z == 1) { W = wk; bias = bk; dst = g_k; }
    else                      { W = wv; bias = bv; dst = g_v; }

    const int m0 = blockIdx.y * 128, n0 = blockIdx.x * 128;
    float acc[8][8] = {};
    gemm_tile(x, W, m0, n0, acc);

    const int tx = threadIdx.x & 15, ty = threadIdx.x >> 4;
    #pragma unroll
    for (int i = 0; i < 8; i++) {
        const int m = m0 + ty*8 + i;
        const int b = m >> 11, s = m & (Ss - 1);
        #pragma unroll
        for (int j = 0; j < 8; j++) {
            const int n = n0 + tx*8 + j;
            const int h = n >> 6, hd = n & 63;
            dst[(((size_t)(b*Hh + h))*Ss + s)*HD + hd] = acc[i][j] + bias[n];
        }
    }
}

// ---------------------------------------------------------------------------
// Output projection: out = g_o @ wo^T + bo
// ---------------------------------------------------------------------------
__global__ __launch_bounds__(256) void outproj_kernel(
    const float* __restrict__ wo, const float* __restrict__ bo,
    float* __restrict__ out)
{
    const int m0 = blockIdx.y * 128, n0 = blockIdx.x * 128;
    float acc[8][8] = {};
    gemm_tile(g_o, wo, m0, n0, acc);

    const int tx = threadIdx.x & 15, ty = threadIdx.x >> 4;
    #pragma unroll
    for (int i = 0; i < 8; i++) {
        const int m = m0 + ty*8 + i;
        #pragma unroll
        for (int j = 0; j < 8; j++) {
            const int n = n0 + tx*8 + j;
            out[(size_t)m*Dd + n] = acc[i][j] + bo[n];
        }
    }
}

// ---------------------------------------------------------------------------
// Flash-style attention + fused Gram-Schmidt exclusion epilogue.
// Block = one (b,h) x 64-query tile. 256 threads, 4x4 micro-tiles.
// Smem: q[64][68], k^T[64(hd)][68(k)], v[64][68], s/p/o[64][68] + row stats.
// ---------------------------------------------------------------------------
#define PAD 68
#define SMEM_FLOATS (4*64*PAD + 128)
#define SMEM_BYTES  (SMEM_FLOATS * 4)

__global__ __launch_bounds__(256) void attn_kernel()
{
    extern __shared__ float sm[];
    float* qs   = sm;                 // [64][PAD]
    float* kst  = sm + 1*64*PAD;      // [64(hd)][PAD(k)]  (transposed)
    float* vs   = sm + 2*64*PAD;      // [64][PAD]
    float* ss   = sm + 3*64*PAD;      // [64][PAD]  scores -> probs -> o
    float* rowf = sm + 4*64*PAD;      // [64] corr / align
    float* lsum = rowf + 64;          // [64]

    const int tid = threadIdx.x;
    const int tx = tid & 15, ty = tid >> 4;
    const int r0 = ty * 4, c0 = tx * 4;
    const int trow = tid >> 2, tq = tid & 3;

    const int q0 = blockIdx.x * 64;
    const int bh = blockIdx.y;
    const float* __restrict__ qptr = g_q + (size_t)bh * Ss * HD;
    const float* __restrict__ kptr = g_k + (size_t)bh * Ss * HD;
    const float* __restrict__ vptr = g_v + (size_t)bh * Ss * HD;

    // load Q tile (row-major, padded)
    #pragma unroll
    for (int i = 0; i < 4; i++) {
        const int idx = tid + i*256;
        const int row = idx >> 4, c4 = (idx & 15) * 4;
        *(float4*)&qs[row*PAD + c4] = *(const float4*)(qptr + (size_t)(q0+row)*HD + c4);
    }

    float m_i = -1e30f, l_i = 0.f;
    float acc[4][4] = {};

    for (int kt = 0; kt < Ss/64; kt++) {
        const int k0 = kt * 64;
        // stage global loads into registers before the barrier
        float4 kv[4], vv[4];
        #pragma unroll
        for (int i = 0; i < 4; i++) {
            const int idx = tid + i*256;
            const int row = idx >> 4, c4 = (idx & 15) * 4;
            kv[i] = *(const float4*)(kptr + (size_t)(k0+row)*HD + c4);
            vv[i] = *(const float4*)(vptr + (size_t)(k0+row)*HD + c4);
        }
        __syncthreads();   // previous iteration done reading kst/vs/ss
        #pragma unroll
        for (int i = 0; i < 4; i++) {
            const int idx = tid + i*256;
            const int row = idx >> 4, c4 = (idx & 15) * 4;
            *(float4*)&vs[row*PAD + c4] = vv[i];
            kst[(c4+0)*PAD + row] = kv[i].x;   // transpose K: [hd][k]
            kst[(c4+1)*PAD + row] = kv[i].y;
            kst[(c4+2)*PAD + row] = kv[i].z;
            kst[(c4+3)*PAD + row] = kv[i].w;
        }
        __syncthreads();

        // S = Q K^T (4x4 per thread)
        float sr[4][4] = {};
        #pragma unroll 8
        for (int d = 0; d < HD; d++) {
            float a[4];
            #pragma unroll
            for (int i = 0; i < 4; i++) a[i] = qs[(r0+i)*PAD + d];
            const float4 b4 = *(const float4*)&kst[d*PAD + c0];
            #pragma unroll
            for (int i = 0; i < 4; i++) {
                sr[i][0] += a[i]*b4.x; sr[i][1] += a[i]*b4.y;
                sr[i][2] += a[i]*b4.z; sr[i][3] += a[i]*b4.w;
            }
        }
        #pragma unroll
        for (int i = 0; i < 4; i++) {
            float4 w = make_float4(sr[i][0]*0.125f, sr[i][1]*0.125f,
                                   sr[i][2]*0.125f, sr[i][3]*0.125f);
            *(float4*)&ss[(r0+i)*PAD + c0] = w;
        }
        __syncthreads();

        // online softmax: 4 threads per row, 16 cols each, shfl-combine
        {
            const int base = trow*PAD + tq*16;
            float mx = -1e30f;
            #pragma unroll
            for (int k = 0; k < 16; k++) mx = fmaxf(mx, ss[base+k]);
            mx = fmaxf(mx, __shfl_xor_sync(0xffffffffu, mx, 1));
            mx = fmaxf(mx, __shfl_xor_sync(0xffffffffu, mx, 2));
            const float mn   = fmaxf(m_i, mx);
            const float corr = __expf(m_i - mn);
            float sump = 0.f;
            #pragma unroll
            for (int k = 0; k < 16; k++) {
                const float p = __expf(ss[base+k] - mn);
                ss[base+k] = p;
                sump += p;
            }
            sump += __shfl_xor_sync(0xffffffffu, sump, 1);
            sump += __shfl_xor_sync(0xffffffffu, sump, 2);
            l_i = l_i * corr + sump;
            m_i = mn;
            if (tq == 0) rowf[trow] = corr;
        }
        __syncthreads();

        // rescale accumulators, then O += P V
        float cr[4];
        #pragma unroll
        for (int i = 0; i < 4; i++) cr[i] = rowf[r0+i];
        #pragma unroll
        for (int i = 0; i < 4; i++)
            #pragma unroll
            for (int j = 0; j < 4; j++) acc[i][j] *= cr[i];

        #pragma unroll 8
        for (int kk = 0; kk < 64; kk++) {
            float p[4];
            #pragma unroll
            for (int i = 0; i < 4; i++) p[i] = ss[(r0+i)*PAD + kk];
            const float4 v4 = *(const float4*)&vs[kk*PAD + c0];
            #pragma unroll
            for (int i = 0; i < 4; i++) {
                acc[i][0] += p[i]*v4.x; acc[i][1] += p[i]*v4.y;
                acc[i][2] += p[i]*v4.z; acc[i][3] += p[i]*v4.w;
            }
        }
        // next iteration's leading __syncthreads() closes the window
    }

    if (tq == 0) lsum[trow] = l_i;
    __syncthreads();     // PV reads done; lsum visible

    // normalized O into ss
    #pragma unroll
    for (int i = 0; i < 4; i++) {
        const float inv = 1.0f / lsum[r0+i];
        float4 w = make_float4(acc[i][0]*inv, acc[i][1]*inv,
                               acc[i][2]*inv, acc[i][3]*inv);
        *(float4*)&ss[(r0+i)*PAD + c0] = w;
    }
    __syncthreads();

    // Gram-Schmidt exclusion: align = (o . v_q) / (v_q . v_q + eps), per row
    {
        const int base = trow*PAD + tq*16;
        const float* vq = vptr + (size_t)(q0 + trow)*HD + tq*16;
        float ov = 0.f, vv2 = 0.f;
        #pragma unroll
        for (int k = 0; k < 16; k++) {
            const float vx = vq[k];
            ov  += ss[base+k] * vx;
            vv2 += vx * vx;
        }
        ov  += __shfl_xor_sync(0xffffffffu, ov, 1);
        ov  += __shfl_xor_sync(0xffffffffu, ov, 2);
        vv2 += __shfl_xor_sync(0xffffffffu, vv2, 1);
        vv2 += __shfl_xor_sync(0xffffffffu, vv2, 2);
        if (tq == 0) rowf[trow] = ov / (vv2 + EPS);
    }
    __syncthreads();

    // o -= align * v_q ; write in [b, s, h*HD+hd] layout for the final GEMM
    const int b = bh >> 4, h = bh & 15;
    #pragma unroll
    for (int i = 0; i < 4; i++) {
        const int row = r0 + i, s = q0 + row;
        const float al = rowf[row];
        const float4 v4 = *(const float4*)(vptr + (size_t)(q0+row)*HD + c0);
        const float4 o4 = *(const float4*)&ss[row*PAD + c0];
        float4 w = make_float4(o4.x - al*v4.x, o4.y - al*v4.y,
                               o4.z - al*v4.z, o4.w - al*v4.w);
        *(float4*)&g_o[((size_t)(b*Ss + s))*Dd + h*HD + c0] = w;
    }
}

// ---------------------------------------------------------------------------
extern "C" void kernel_launch(void* const* d_in, const int* in_sizes, int n_in,
                              void* d_out, int out_size)
{
    const float* x  = (const float*)d_in[0];
    const float* wq = (const float*)d_in[1];
    const float* bq = (const float*)d_in[2];
    const float* wk = (const float*)d_in[3];
    const float* bk = (const float*)d_in[4];
    const float* wv = (const float*)d_in[5];
    const float* bv = (const float*)d_in[6];
    const float* wo = (const float*)d_in[7];
    const float* bo = (const float*)d_in[8];
    float* out = (float*)d_out;

    // Unconditional + idempotent (no static guards per harness rules; not a
    // stream-ordered op, so graph capture is unaffected).
    cudaFuncSetAttribute(attn_kernel,
                         cudaFuncAttributeMaxDynamicSharedMemorySize, SMEM_BYTES);

    dim3 gqkv(Dd/128, Mm/128, 3);
    qkv_kernel<<<gqkv, 256>>>(x, wq, bq, wk, bk, wv, bv);

    dim3 gat(Ss/64, Bb*Hh);
    attn_kernel<<<gat, 256, SMEM_BYTES>>>();

    dim3 gop(Dd/128, Mm/128);
    outproj_kernel<<<gop, 256>>>(wo, bo, out);
}

// round 14
// speedup vs baseline: 1.0102x; 1.0102x over previous
#include <cuda_runtime.h>

// Problem constants
#define Bb   2
#define Ss   2048
#define Dd   1024
#define Hh   16
#define HD   64
#define Mm   (Bb*Ss)          // 4096
#define EPS  1e-8f

// Scratch (allocation-free rule: __device__ globals)
__device__ float g_q[Bb*Hh*Ss*HD];
__device__ float g_k[Bb*Hh*Ss*HD];
__device__ float g_v[Bb*Hh*Ss*HD];
__device__ float g_o[Mm*Dd];

// ---------------------------------------------------------------------------
// Packed f32x2 primitives (sm_103a FFMA2 — ptxas won't emit these from C++)
// ---------------------------------------------------------------------------
typedef unsigned long long u64;

__device__ __forceinline__ void fma2(u64& d, u64 a, u64 b, u64 c) {
    asm("fma.rn.f32x2 %0, %1, %2, %3;" : "=l"(d) : "l"(a), "l"(b), "l"(c));
}
__device__ __forceinline__ void mul2(u64& d, u64 a, u64 b) {
    asm("mul.rn.f32x2 %0, %1, %2;" : "=l"(d) : "l"(a), "l"(b));
}
__device__ __forceinline__ u64 bcast2(float x) {
    u64 r;
    asm("mov.b64 %0, {%1, %1};" : "=l"(r) : "r"(__float_as_uint(x)));
    return r;
}
__device__ __forceinline__ float lo2(u64 v) { return __uint_as_float((unsigned)v); }
__device__ __forceinline__ float hi2(u64 v) { return __uint_as_float((unsigned)(v >> 32)); }

// ---------------------------------------------------------------------------
// SGEMM core: C[128x128] tile of A[M,K] * W[N,K]^T, packed-f32x2 inner loop.
// 256 threads, 8x8 micro-tile (as 8x4 f32x2 pairs), BK=8, double-buffered.
// ---------------------------------------------------------------------------
__device__ __forceinline__ void gemm_tile(
    const float* __restrict__ A, const float* __restrict__ W,
    int m0, int n0, u64 acc2[8][4])
{
    __shared__ __align__(16) float As[2][8][128];
    __shared__ __align__(16) float Bs[2][8][128];
    const int tid = threadIdx.x;
    const int tx  = tid & 15, ty = tid >> 4;
    const int lrow = tid >> 1;            // 0..127
    const int lc4  = (tid & 1) * 4;       // 0 or 4
    const float* aptr = A + (size_t)(m0 + lrow) * Dd + lc4;
    const float* bptr = W + (size_t)(n0 + lrow) * Dd + lc4;

    // prologue: fill buffer 0
    float4 av = *(const float4*)(aptr);
    float4 bv = *(const float4*)(bptr);
    As[0][lc4+0][lrow] = av.x; As[0][lc4+1][lrow] = av.y;
    As[0][lc4+2][lrow] = av.z; As[0][lc4+3][lrow] = av.w;
    Bs[0][lc4+0][lrow] = bv.x; Bs[0][lc4+1][lrow] = bv.y;
    Bs[0][lc4+2][lrow] = bv.z; Bs[0][lc4+3][lrow] = bv.w;
    __syncthreads();

    int buf = 0;
    for (int k0 = 0; k0 < Dd; k0 += 8) {
        const bool has_next = (k0 + 8) < Dd;
        if (has_next) {
            av = *(const float4*)(aptr + k0 + 8);
            bv = *(const float4*)(bptr + k0 + 8);
        }
        #pragma unroll
        for (int k = 0; k < 8; k++) {
            float a[8];
            *(float4*)&a[0] = *(const float4*)&As[buf][k][ty*8];
            *(float4*)&a[4] = *(const float4*)&As[buf][k][ty*8+4];
            u64 b2[4];
            *(ulonglong2*)&b2[0] = *(const ulonglong2*)&Bs[buf][k][tx*8];
            *(ulonglong2*)&b2[2] = *(const ulonglong2*)&Bs[buf][k][tx*8+4];
            #pragma unroll
            for (int i = 0; i < 8; i++) {
                const u64 a2 = bcast2(a[i]);
                #pragma unroll
                for (int jp = 0; jp < 4; jp++)
                    fma2(acc2[i][jp], a2, b2[jp], acc2[i][jp]);
            }
        }
        if (has_next) {
            const int nb = buf ^ 1;
            As[nb][lc4+0][lrow] = av.x; As[nb][lc4+1][lrow] = av.y;
            As[nb][lc4+2][lrow] = av.z; As[nb][lc4+3][lrow] = av.w;
            Bs[nb][lc4+0][lrow] = bv.x; Bs[nb][lc4+1][lrow] = bv.y;
            Bs[nb][lc4+2][lrow] = bv.z; Bs[nb][lc4+3][lrow] = bv.w;
            __syncthreads();
            buf = nb;
        }
    }
}

// ---------------------------------------------------------------------------
// Fused QKV projection. gridDim.z = 3 selects (W, bias, dst).
// Stores into [b, h, s, hd] layout for the attention kernel.
// ---------------------------------------------------------------------------
__global__ __launch_bounds__(256) void qkv_kernel(
    const float* __restrict__ x,
    const float* __restrict__ wq, const float* __restrict__ bq,
    const float* __restrict__ wk, const float* __restrict__ bk,
    const float* __restrict__ wv, const float* __restrict__ bv)
{
    const float* W; const float* bias; float* dst;
    if (blockIdx.z == 0)      { W = wq; bias = bq; dst = g_q; }
    else if (blockIdx.z == 1) { W = wk; bias = bk; dst = g_k; }
    else                      { W = wv; bias = bv; dst = g_v; }

    const int m0 = blockIdx.y * 128, n0 = blockIdx.x * 128;
    u64 acc2[8][4] = {};
    gemm_tile(x, W, m0, n0, acc2);

    const int tx = threadIdx.x & 15, ty = threadIdx.x >> 4;
    #pragma unroll
    for (int i = 0; i < 8; i++) {
        const int m = m0 + ty*8 + i;
        const int b = m >> 11, s = m & (Ss - 1);
        #pragma unroll
        for (int jp = 0; jp < 4; jp++) {
            const int n_lo = n0 + tx*8 + 2*jp;
            const int n_hi = n_lo + 1;
            const int h_lo = n_lo >> 6, hd_lo = n_lo & 63;
            const int h_hi = n_hi >> 6, hd_hi = n_hi & 63;
            dst[(((size_t)(b*Hh + h_lo))*Ss + s)*HD + hd_lo] = lo2(acc2[i][jp]) + bias[n_lo];
            dst[(((size_t)(b*Hh + h_hi))*Ss + s)*HD + hd_hi] = hi2(acc2[i][jp]) + bias[n_hi];
        }
    }
}

// ---------------------------------------------------------------------------
// Output projection: out = g_o @ wo^T + bo
// ---------------------------------------------------------------------------
__global__ __launch_bounds__(256) void outproj_kernel(
    const float* __restrict__ wo, const float* __restrict__ bo,
    float* __restrict__ out)
{
    const int m0 = blockIdx.y * 128, n0 = blockIdx.x * 128;
    u64 acc2[8][4] = {};
    gemm_tile(g_o, wo, m0, n0, acc2);

    const int tx = threadIdx.x & 15, ty = threadIdx.x >> 4;
    #pragma unroll
    for (int i = 0; i < 8; i++) {
        const int m = m0 + ty*8 + i;
        #pragma unroll
        for (int jp = 0; jp < 4; jp++) {
            const int n = n0 + tx*8 + 2*jp;
            out[(size_t)m*Dd + n]     = lo2(acc2[i][jp]) + bo[n];
            out[(size_t)m*Dd + n + 1] = hi2(acc2[i][jp]) + bo[n + 1];
        }
    }
}

// ---------------------------------------------------------------------------
// Flash-style attention + fused Gram-Schmidt exclusion epilogue.
// Block = one (b,h) x 64-query tile. 256 threads, 4x4 micro-tiles
// (computed as 4x2 f32x2 pairs). Softmax/epilogue unchanged (scalar).
// ---------------------------------------------------------------------------
#define PAD 68
#define SMEM_FLOATS (4*64*PAD + 128)
#define SMEM_BYTES  (SMEM_FLOATS * 4)

__global__ __launch_bounds__(256) void attn_kernel()
{
    extern __shared__ float sm[];
    float* qs   = sm;                 // [64][PAD]
    float* kst  = sm + 1*64*PAD;      // [64(hd)][PAD(k)]  (transposed)
    float* vs   = sm + 2*64*PAD;      // [64][PAD]
    float* ss   = sm + 3*64*PAD;      // [64][PAD]  scores -> probs -> o
    float* rowf = sm + 4*64*PAD;      // [64] corr / align
    float* lsum = rowf + 64;          // [64]

    const int tid = threadIdx.x;
    const int tx = tid & 15, ty = tid >> 4;
    const int r0 = ty * 4, c0 = tx * 4;
    const int trow = tid >> 2, tq = tid & 3;

    const int q0 = blockIdx.x * 64;
    const int bh = blockIdx.y;
    const float* __restrict__ qptr = g_q + (size_t)bh * Ss * HD;
    const float* __restrict__ kptr = g_k + (size_t)bh * Ss * HD;
    const float* __restrict__ vptr = g_v + (size_t)bh * Ss * HD;

    // load Q tile (row-major, padded)
    #pragma unroll
    for (int i = 0; i < 4; i++) {
        const int idx = tid + i*256;
        const int row = idx >> 4, c4 = (idx & 15) * 4;
        *(float4*)&qs[row*PAD + c4] = *(const float4*)(qptr + (size_t)(q0+row)*HD + c4);
    }

    float m_i = -1e30f, l_i = 0.f;
    u64 acc2[4][2] = {};                 // packed O accumulators (cols c0..c0+3)
    const u64 eighth2 = bcast2(0.125f);  // 1/sqrt(64)

    for (int kt = 0; kt < Ss/64; kt++) {
        const int k0 = kt * 64;
        // stage global loads into registers before the barrier
        float4 kv[4], vv[4];
        #pragma unroll
        for (int i = 0; i < 4; i++) {
            const int idx = tid + i*256;
            const int row = idx >> 4, c4 = (idx & 15) * 4;
            kv[i] = *(const float4*)(kptr + (size_t)(k0+row)*HD + c4);
            vv[i] = *(const float4*)(vptr + (size_t)(k0+row)*HD + c4);
        }
        __syncthreads();   // previous iteration done reading kst/vs/ss
        #pragma unroll
        for (int i = 0; i < 4; i++) {
            const int idx = tid + i*256;
            const int row = idx >> 4, c4 = (idx & 15) * 4;
            *(float4*)&vs[row*PAD + c4] = vv[i];
            kst[(c4+0)*PAD + row] = kv[i].x;   // transpose K: [hd][k]
            kst[(c4+1)*PAD + row] = kv[i].y;
            kst[(c4+2)*PAD + row] = kv[i].z;
            kst[(c4+3)*PAD + row] = kv[i].w;
        }
        __syncthreads();

        // S = Q K^T (4 rows x 2 f32x2-pairs per thread)
        u64 sr2[4][2] = {};
        #pragma unroll 8
        for (int d = 0; d < HD; d++) {
            float a[4];
            #pragma unroll
            for (int i = 0; i < 4; i++) a[i] = qs[(r0+i)*PAD + d];
            u64 b2[2];
            *(ulonglong2*)&b2[0] = *(const ulonglong2*)&kst[d*PAD + c0];
            #pragma unroll
            for (int i = 0; i < 4; i++) {
                const u64 a2 = bcast2(a[i]);
                fma2(sr2[i][0], a2, b2[0], sr2[i][0]);
                fma2(sr2[i][1], a2, b2[1], sr2[i][1]);
            }
        }
        #pragma unroll
        for (int i = 0; i < 4; i++) {
            ulonglong2 w;
            mul2(w.x, sr2[i][0], eighth2);
            mul2(w.y, sr2[i][1], eighth2);
            *(ulonglong2*)&ss[(r0+i)*PAD + c0] = w;
        }
        __syncthreads();

        // online softmax: 4 threads per row, 16 cols each, shfl-combine
        {
            const int base = trow*PAD + tq*16;
            float mx = -1e30f;
            #pragma unroll
            for (int k = 0; k < 16; k++) mx = fmaxf(mx, ss[base+k]);
            mx = fmaxf(mx, __shfl_xor_sync(0xffffffffu, mx, 1));
            mx = fmaxf(mx, __shfl_xor_sync(0xffffffffu, mx, 2));
            const float mn   = fmaxf(m_i, mx);
            const float corr = __expf(m_i - mn);
            float sump = 0.f;
            #pragma unroll
            for (int k = 0; k < 16; k++) {
                const float p = __expf(ss[base+k] - mn);
                ss[base+k] = p;
                sump += p;
            }
            sump += __shfl_xor_sync(0xffffffffu, sump, 1);
            sump += __shfl_xor_sync(0xffffffffu, sump, 2);
            l_i = l_i * corr + sump;
            m_i = mn;
            if (tq == 0) rowf[trow] = corr;
        }
        __syncthreads();

        // rescale accumulators (packed), then O += P V (packed)
        #pragma unroll
        for (int i = 0; i < 4; i++) {
            const u64 cr2 = bcast2(rowf[r0+i]);
            mul2(acc2[i][0], acc2[i][0], cr2);
            mul2(acc2[i][1], acc2[i][1], cr2);
        }

        #pragma unroll 8
        for (int kk = 0; kk < 64; kk++) {
            float p[4];
            #pragma unroll
            for (int i = 0; i < 4; i++) p[i] = ss[(r0+i)*PAD + kk];
            u64 v2[2];
            *(ulonglong2*)&v2[0] = *(const ulonglong2*)&vs[kk*PAD + c0];
            #pragma unroll
            for (int i = 0; i < 4; i++) {
                const u64 p2 = bcast2(p[i]);
                fma2(acc2[i][0], p2, v2[0], acc2[i][0]);
                fma2(acc2[i][1], p2, v2[1], acc2[i][1]);
            }
        }
        // next iteration's leading __syncthreads() closes the window
    }

    if (tq == 0) lsum[trow] = l_i;
    __syncthreads();     // PV reads done; lsum visible

    // normalized O into ss (packed mul, identical arithmetic)
    #pragma unroll
    for (int i = 0; i < 4; i++) {
        const u64 inv2 = bcast2(1.0f / lsum[r0+i]);
        ulonglong2 w;
        mul2(w.x, acc2[i][0], inv2);
        mul2(w.y, acc2[i][1], inv2);
        *(ulonglong2*)&ss[(r0+i)*PAD + c0] = w;
    }
    __syncthreads();

    // Gram-Schmidt exclusion: align = (o . v_q) / (v_q . v_q + eps), per row
    {
        const int base = trow*PAD + tq*16;
        const float* vq = vptr + (size_t)(q0 + trow)*HD + tq*16;
        float ov = 0.f, vv2 = 0.f;
        #pragma unroll
        for (int k = 0; k < 16; k++) {
            const float vx = vq[k];
            ov  += ss[base+k] * vx;
            vv2 += vx * vx;
        }
        ov  += __shfl_xor_sync(0xffffffffu, ov, 1);
        ov  += __shfl_xor_sync(0xffffffffu, ov, 2);
        vv2 += __shfl_xor_sync(0xffffffffu, vv2, 1);
        vv2 += __shfl_xor_sync(0xffffffffu, vv2, 2);
        if (tq == 0) rowf[trow] = ov / (vv2 + EPS);
    }
    __syncthreads();

    // o -= align * v_q ; write in [b, s, h*HD+hd] layout for the final GEMM
    const int b = bh >> 4, h = bh & 15;
    #pragma unroll
    for (int i = 0; i < 4; i++) {
        const int row = r0 + i, s = q0 + row;
        const float al = rowf[row];
        const float4 v4 = *(const float4*)(vptr + (size_t)(q0+row)*HD + c0);
        const float4 o4 = *(const float4*)&ss[row*PAD + c0];
        float4 w = make_float4(o4.x - al*v4.x, o4.y - al*v4.y,
                               o4.z - al*v4.z, o4.w - al*v4.w);
        *(float4*)&g_o[((size_t)(b*Ss + s))*Dd + h*HD + c0] = w;
    }
}

// ---------------------------------------------------------------------------
extern "C" void kernel_launch(void* const* d_in, const int* in_sizes, int n_in,
                              void* d_out, int out_size)
{
    const float* x  = (const float*)d_in[0];
    const float* wq = (const float*)d_in[1];
    const float* bq = (const float*)d_in[2];
    const float* wk = (const float*)d_in[3];
    const float* bk = (const float*)d_in[4];
    const float* wv = (const float*)d_in[5];
    const float* bv = (const float*)d_in[6];
    const float* wo = (const float*)d_in[7];
    const float* bo = (const float*)d_in[8];
    float* out = (float*)d_out;

    cudaFuncSetAttribute(attn_kernel,
                         cudaFuncAttributeMaxDynamicSharedMemorySize, SMEM_BYTES);

    dim3 gqkv(Dd/128, Mm/128, 3);
    qkv_kernel<<<gqkv, 256>>>(x, wq, bq, wk, bk, wv, bv);

    dim3 gat(Ss/64, Bb*Hh);
    attn_kernel<<<gat, 256, SMEM_BYTES>>>();

    dim3 gop(Dd/128, Mm/128);
    outproj_kernel<<<gop, 256>>>(wo, bo, out);
}